// round 1
// baseline (speedup 1.0000x reference)
#include <cuda_runtime.h>

#define NN 50000
#define NE 640000
#define EMB 128

// ---- scratch (device globals; no runtime allocation allowed) ----
__device__ float g_hA[NN * EMB];      // 25.6 MB
__device__ float g_hB[NN * EMB];      // 25.6 MB
__device__ float g_norm_src[NN];
__device__ float g_norm_dst[NN];
__device__ int   g_deg_src[NN];
__device__ int   g_deg_dst[NN];
__device__ int   g_row_ptr[NN + 1];
__device__ int   g_cursor[NN];
__device__ int   g_col[NE];
__device__ float g_colw[NE];

// ---------------------------------------------------------------
__global__ void k_zero_deg() {
    int i = blockIdx.x * blockDim.x + threadIdx.x;
    if (i < NN) { g_deg_src[i] = 0; g_deg_dst[i] = 0; }
}

__global__ void k_count(const int* __restrict__ src, const int* __restrict__ dst) {
    int e = blockIdx.x * blockDim.x + threadIdx.x;
    if (e < NE) {
        atomicAdd(&g_deg_src[src[e]], 1);
        atomicAdd(&g_deg_dst[dst[e]], 1);
    }
}

__global__ void k_norm() {
    int i = blockIdx.x * blockDim.x + threadIdx.x;
    if (i < NN) {
        g_norm_src[i] = rsqrtf((float)max(g_deg_src[i], 1));
        g_norm_dst[i] = rsqrtf((float)max(g_deg_dst[i], 1));
    }
}

// single-block exclusive scan of g_deg_dst -> g_row_ptr (+ g_cursor copy)
__global__ void k_scan() {
    __shared__ int part[1024];
    int tid = threadIdx.x;
    const int CH = (NN + 1023) / 1024;  // 49
    int s0 = tid * CH;
    int s1 = min(s0 + CH, NN);
    int s = 0;
    for (int i = s0; i < s1; i++) s += g_deg_dst[i];
    part[tid] = s;
    __syncthreads();
    // Hillis-Steele inclusive scan
    for (int off = 1; off < 1024; off <<= 1) {
        int v = (tid >= off) ? part[tid - off] : 0;
        __syncthreads();
        part[tid] += v;
        __syncthreads();
    }
    int run = (tid == 0) ? 0 : part[tid - 1];
    for (int i = s0; i < s1; i++) {
        g_row_ptr[i] = run;
        g_cursor[i]  = run;
        run += g_deg_dst[i];
    }
    if (tid == 0) g_row_ptr[NN] = part[1023];
}

__global__ void k_fill(const int* __restrict__ src, const int* __restrict__ dst) {
    int e = blockIdx.x * blockDim.x + threadIdx.x;
    if (e < NE) {
        int s = src[e];
        int pos = atomicAdd(&g_cursor[dst[e]], 1);
        g_col[pos]  = s;
        g_colw[pos] = g_norm_src[s];   // fold src-side norm into edge weight
    }
}

// h = node_feats @ W_emb + b_emb   (IN_DIM = 4)
__global__ void k_embed(const float* __restrict__ nf,
                        const float* __restrict__ W,
                        const float* __restrict__ b) {
    int idx = blockIdx.x * blockDim.x + threadIdx.x;
    if (idx >= NN * EMB) return;
    int node = idx >> 7;
    int c = idx & 127;
    float a0 = nf[node * 4 + 0];
    float a1 = nf[node * 4 + 1];
    float a2 = nf[node * 4 + 2];
    float a3 = nf[node * 4 + 3];
    float acc = b[c];
    acc += a0 * W[0 * 128 + c];
    acc += a1 * W[1 * 128 + c];
    acc += a2 * W[2 * 128 + c];
    acc += a3 * W[3 * 128 + c];
    g_hA[idx] = acc;
}

// CSR aggregation: one warp per destination node, lane owns 4 floats (float4)
__global__ void k_spmm(const float* __restrict__ h, float* __restrict__ out) {
    int gw = (blockIdx.x * blockDim.x + threadIdx.x) >> 5;
    int lane = threadIdx.x & 31;
    if (gw >= NN) return;
    int beg = g_row_ptr[gw];
    int end = g_row_ptr[gw + 1];
    float4 acc = make_float4(0.f, 0.f, 0.f, 0.f);
    int j = beg;
    for (; j + 2 <= end; j += 2) {
        int   s0 = __ldg(&g_col[j]);
        int   s1 = __ldg(&g_col[j + 1]);
        float w0 = __ldg(&g_colw[j]);
        float w1 = __ldg(&g_colw[j + 1]);
        float4 v0 = *(const float4*)(h + (size_t)s0 * EMB + lane * 4);
        float4 v1 = *(const float4*)(h + (size_t)s1 * EMB + lane * 4);
        acc.x += w0 * v0.x + w1 * v1.x;
        acc.y += w0 * v0.y + w1 * v1.y;
        acc.z += w0 * v0.z + w1 * v1.z;
        acc.w += w0 * v0.w + w1 * v1.w;
    }
    if (j < end) {
        int   s0 = __ldg(&g_col[j]);
        float w0 = __ldg(&g_colw[j]);
        float4 v0 = *(const float4*)(h + (size_t)s0 * EMB + lane * 4);
        acc.x += w0 * v0.x;
        acc.y += w0 * v0.y;
        acc.z += w0 * v0.z;
        acc.w += w0 * v0.w;
    }
    float nd = g_norm_dst[gw];
    acc.x *= nd; acc.y *= nd; acc.z *= nd; acc.w *= nd;
    *(float4*)(out + (size_t)gw * EMB + lane * 4) = acc;
}

// C[M,128] = act(A[M,128] @ W[128,128] + bias)
// block: 256 threads, tile 128 rows x 128 cols, micro-tile 8x8, BK=16
template <bool RELU>
__global__ void __launch_bounds__(256)
k_gemm(const float* __restrict__ A, const float* __restrict__ W,
       const float* __restrict__ bias, float* __restrict__ C, int M) {
    __shared__ float As[16][128];   // As[k][m] (A tile transposed)
    __shared__ float Bs[16][128];   // Bs[k][n]
    int tid  = threadIdx.x;
    int row0 = blockIdx.x * 128;
    int trow = (tid >> 4) << 3;     // 0..120
    int tcol = (tid & 15) << 3;     // 0..120
    float acc[8][8] = {};

    for (int k0 = 0; k0 < 128; k0 += 16) {
        // load A tile (128x16): 512 float4s, 2 per thread
        #pragma unroll
        for (int half = 0; half < 2; half++) {
            int f  = tid + half * 256;
            int m  = f >> 2;
            int kq = (f & 3) << 2;
            int gr = row0 + m;
            float4 a = (gr < M) ? *(const float4*)(A + (size_t)gr * 128 + k0 + kq)
                                : make_float4(0.f, 0.f, 0.f, 0.f);
            As[kq + 0][m] = a.x;
            As[kq + 1][m] = a.y;
            As[kq + 2][m] = a.z;
            As[kq + 3][m] = a.w;
        }
        // load B tile (16x128): 512 float4s, 2 per thread
        #pragma unroll
        for (int half = 0; half < 2; half++) {
            int f = tid + half * 256;
            int k = f >> 5;
            int n = (f & 31) << 2;
            *(float4*)&Bs[k][n] = *(const float4*)(W + (size_t)(k0 + k) * 128 + n);
        }
        __syncthreads();

        #pragma unroll
        for (int k = 0; k < 16; k++) {
            float a[8], b[8];
            *(float4*)&a[0] = *(const float4*)&As[k][trow];
            *(float4*)&a[4] = *(const float4*)&As[k][trow + 4];
            *(float4*)&b[0] = *(const float4*)&Bs[k][tcol];
            *(float4*)&b[4] = *(const float4*)&Bs[k][tcol + 4];
            #pragma unroll
            for (int i = 0; i < 8; i++)
                #pragma unroll
                for (int jj = 0; jj < 8; jj++)
                    acc[i][jj] += a[i] * b[jj];
        }
        __syncthreads();
    }

    float bv[8];
    *(float4*)&bv[0] = *(const float4*)&bias[tcol];
    *(float4*)&bv[4] = *(const float4*)&bias[tcol + 4];
    #pragma unroll
    for (int i = 0; i < 8; i++) {
        int gr = row0 + trow + i;
        if (gr < M) {
            float4 o0, o1;
            o0.x = acc[i][0] + bv[0];
            o0.y = acc[i][1] + bv[1];
            o0.z = acc[i][2] + bv[2];
            o0.w = acc[i][3] + bv[3];
            o1.x = acc[i][4] + bv[4];
            o1.y = acc[i][5] + bv[5];
            o1.z = acc[i][6] + bv[6];
            o1.w = acc[i][7] + bv[7];
            if (RELU) {
                o0.x = fmaxf(o0.x, 0.f); o0.y = fmaxf(o0.y, 0.f);
                o0.z = fmaxf(o0.z, 0.f); o0.w = fmaxf(o0.w, 0.f);
                o1.x = fmaxf(o1.x, 0.f); o1.y = fmaxf(o1.y, 0.f);
                o1.z = fmaxf(o1.z, 0.f); o1.w = fmaxf(o1.w, 0.f);
            }
            *(float4*)(C + (size_t)gr * 128 + tcol)     = o0;
            *(float4*)(C + (size_t)gr * 128 + tcol + 4) = o1;
        }
    }
}

// out[n] = h[n,:] . w2 + b2   (warp per node, warp-shuffle reduce)
__global__ void k_gemv(const float* __restrict__ h, const float* __restrict__ w2,
                       const float* __restrict__ b2, float* __restrict__ out) {
    int gw = (blockIdx.x * blockDim.x + threadIdx.x) >> 5;
    int lane = threadIdx.x & 31;
    if (gw >= NN) return;
    float4 v = *(const float4*)(h + (size_t)gw * 128 + lane * 4);
    float4 w = *(const float4*)(w2 + lane * 4);
    float s = v.x * w.x + v.y * w.y + v.z * w.z + v.w * w.w;
    #pragma unroll
    for (int o = 16; o; o >>= 1) s += __shfl_xor_sync(0xffffffffu, s, o);
    if (lane == 0) out[gw] = s + b2[0];
}

// ---------------------------------------------------------------
extern "C" void kernel_launch(void* const* d_in, const int* in_sizes, int n_in,
                              void* d_out, int out_size) {
    const float* nf   = (const float*)d_in[0];
    const int*   src  = (const int*)d_in[1];
    const int*   dst  = (const int*)d_in[2];
    const float* Wemb = (const float*)d_in[3];
    const float* bemb = (const float*)d_in[4];
    const float* Wg   = (const float*)d_in[5];
    const float* bg   = (const float*)d_in[6];
    const float* Wo1  = (const float*)d_in[7];
    const float* bo1  = (const float*)d_in[8];
    const float* Wo2  = (const float*)d_in[9];
    const float* bo2  = (const float*)d_in[10];
    float* out = (float*)d_out;

    float *hA, *hB;
    cudaGetSymbolAddress((void**)&hA, g_hA);
    cudaGetSymbolAddress((void**)&hB, g_hB);

    const int NB_NODE = (NN + 255) / 256;
    const int NB_EDGE = (NE + 255) / 256;
    const int NB_WARP = (NN * 32 + 255) / 256;   // warp-per-node kernels
    const int NB_GEMM = (NN + 127) / 128;

    k_zero_deg<<<NB_NODE, 256>>>();
    k_count<<<NB_EDGE, 256>>>(src, dst);
    k_norm<<<NB_NODE, 256>>>();
    k_scan<<<1, 1024>>>();
    k_fill<<<NB_EDGE, 256>>>(src, dst);
    k_embed<<<(NN * EMB + 255) / 256, 256>>>(nf, Wemb, bemb);

    for (int l = 0; l < 3; l++) {
        k_spmm<<<NB_WARP, 256>>>(hA, hB);
        k_gemm<true><<<NB_GEMM, 256>>>(hB, Wg + (size_t)l * 128 * 128,
                                       bg + (size_t)l * 128, hA, NN);
    }
    k_gemm<true><<<NB_GEMM, 256>>>(hA, Wo1, bo1, hB, NN);
    k_gemv<<<NB_WARP, 256>>>(hB, Wo2, bo2, out);
}

// round 2
// speedup vs baseline: 1.2736x; 1.2736x over previous
#include <cuda_runtime.h>

#define NN 50000
#define NE 640000
#define EMB 128
#define SCAN_BLOCKS 196   // 196*256 = 50176 >= NN

// ---- scratch (device globals; zero-initialized at load, re-zeroed each launch) ----
__device__ float g_hA[NN * EMB];      // 25.6 MB
__device__ float g_hB[NN * EMB];      // 25.6 MB
__device__ float g_norm_src[NN];
__device__ float g_norm_dst[NN];
__device__ int   g_deg_src[NN];       // zeroed at end of scanB each launch
__device__ int   g_deg_dst[NN];
__device__ int   g_row_ptr[NN + 1];
__device__ int   g_cursor[NN];
__device__ int   g_col[NE];
__device__ float g_colw[NE];
__device__ int   g_part[SCAN_BLOCKS];

// ---------------------------------------------------------------
// h = node_feats @ W_emb + b_emb   (IN_DIM = 4)
__global__ void k_embed(const float* __restrict__ nf,
                        const float* __restrict__ W,
                        const float* __restrict__ b) {
    int idx = blockIdx.x * blockDim.x + threadIdx.x;
    if (idx >= NN * EMB) return;
    int node = idx >> 7;
    int c = idx & 127;
    float a0 = nf[node * 4 + 0];
    float a1 = nf[node * 4 + 1];
    float a2 = nf[node * 4 + 2];
    float a3 = nf[node * 4 + 3];
    float acc = b[c];
    acc += a0 * W[0 * 128 + c];
    acc += a1 * W[1 * 128 + c];
    acc += a2 * W[2 * 128 + c];
    acc += a3 * W[3 * 128 + c];
    g_hA[idx] = acc;
}

__global__ void k_count(const int* __restrict__ src, const int* __restrict__ dst) {
    int e = blockIdx.x * blockDim.x + threadIdx.x;
    if (e < NE) {
        atomicAdd(&g_deg_src[src[e]], 1);
        atomicAdd(&g_deg_dst[dst[e]], 1);
    }
}

// per-block partial sums of deg_dst (256 elems / block)
__global__ void k_scanA() {
    __shared__ int sh[256];
    int i = blockIdx.x * 256 + threadIdx.x;
    int d = (i < NN) ? g_deg_dst[i] : 0;
    sh[threadIdx.x] = d;
    __syncthreads();
    #pragma unroll
    for (int off = 128; off; off >>= 1) {
        if (threadIdx.x < off) sh[threadIdx.x] += sh[threadIdx.x + off];
        __syncthreads();
    }
    if (threadIdx.x == 0) g_part[blockIdx.x] = sh[0];
}

// block b: prefix = sum(part[0..b-1]); local exclusive scan; write row_ptr/cursor;
// also compute both norms and zero the degree counters for the next launch.
__global__ void k_scanB() {
    __shared__ int sh[256];
    __shared__ int pre;
    int tid = threadIdx.x;
    int b = blockIdx.x;
    // prefix of earlier blocks
    int pv = (tid < b) ? g_part[tid] : 0;
    sh[tid] = pv;
    __syncthreads();
    #pragma unroll
    for (int off = 128; off; off >>= 1) {
        if (tid < off) sh[tid] += sh[tid + off];
        __syncthreads();
    }
    if (tid == 0) pre = sh[0];
    __syncthreads();
    int prefix = pre;
    __syncthreads();

    int i = b * 256 + tid;
    int d = (i < NN) ? g_deg_dst[i] : 0;
    // inclusive scan over the block's 256 degrees
    sh[tid] = d;
    __syncthreads();
    #pragma unroll
    for (int off = 1; off < 256; off <<= 1) {
        int v = (tid >= off) ? sh[tid - off] : 0;
        __syncthreads();
        sh[tid] += v;
        __syncthreads();
    }
    int incl = sh[tid];
    int excl = incl - d;
    if (i < NN) {
        int base = prefix + excl;
        g_row_ptr[i] = base;
        g_cursor[i]  = base;
        if (i == NN - 1) g_row_ptr[NN] = prefix + incl;
        int ds = g_deg_src[i];
        g_norm_dst[i] = rsqrtf((float)max(d, 1));
        g_norm_src[i] = rsqrtf((float)max(ds, 1));
        g_deg_dst[i] = 0;   // leave zeroed for next launch
        g_deg_src[i] = 0;
    }
}

__global__ void k_fill(const int* __restrict__ src, const int* __restrict__ dst) {
    int e = blockIdx.x * blockDim.x + threadIdx.x;
    if (e < NE) {
        int s = src[e];
        int pos = atomicAdd(&g_cursor[dst[e]], 1);
        g_col[pos]  = s;
        g_colw[pos] = g_norm_src[s];   // fold src-side norm into edge weight
    }
}

// CSR aggregation: one warp per destination node, lane owns 4 floats (float4)
__global__ void k_spmm(const float* __restrict__ h, float* __restrict__ out) {
    int gw = (blockIdx.x * blockDim.x + threadIdx.x) >> 5;
    int lane = threadIdx.x & 31;
    if (gw >= NN) return;
    int beg = g_row_ptr[gw];
    int end = g_row_ptr[gw + 1];
    float4 acc = make_float4(0.f, 0.f, 0.f, 0.f);
    int j = beg;
    for (; j + 4 <= end; j += 4) {
        int   s0 = __ldg(&g_col[j]);
        int   s1 = __ldg(&g_col[j + 1]);
        int   s2 = __ldg(&g_col[j + 2]);
        int   s3 = __ldg(&g_col[j + 3]);
        float w0 = __ldg(&g_colw[j]);
        float w1 = __ldg(&g_colw[j + 1]);
        float w2 = __ldg(&g_colw[j + 2]);
        float w3 = __ldg(&g_colw[j + 3]);
        float4 v0 = *(const float4*)(h + (size_t)s0 * EMB + lane * 4);
        float4 v1 = *(const float4*)(h + (size_t)s1 * EMB + lane * 4);
        float4 v2 = *(const float4*)(h + (size_t)s2 * EMB + lane * 4);
        float4 v3 = *(const float4*)(h + (size_t)s3 * EMB + lane * 4);
        acc.x += w0 * v0.x + w1 * v1.x + w2 * v2.x + w3 * v3.x;
        acc.y += w0 * v0.y + w1 * v1.y + w2 * v2.y + w3 * v3.y;
        acc.z += w0 * v0.z + w1 * v1.z + w2 * v2.z + w3 * v3.z;
        acc.w += w0 * v0.w + w1 * v1.w + w2 * v2.w + w3 * v3.w;
    }
    for (; j < end; j++) {
        int   s0 = __ldg(&g_col[j]);
        float w0 = __ldg(&g_colw[j]);
        float4 v0 = *(const float4*)(h + (size_t)s0 * EMB + lane * 4);
        acc.x += w0 * v0.x;
        acc.y += w0 * v0.y;
        acc.z += w0 * v0.z;
        acc.w += w0 * v0.w;
    }
    float nd = g_norm_dst[gw];
    acc.x *= nd; acc.y *= nd; acc.z *= nd; acc.w *= nd;
    *(float4*)(out + (size_t)gw * EMB + lane * 4) = acc;
}

// C[M,128] = act(A[M,128] @ W[128,128] + bias)
// block: 256 threads, tile 128 rows x 128 cols, micro-tile 8x8, BK=16
template <bool RELU>
__global__ void __launch_bounds__(256)
k_gemm(const float* __restrict__ A, const float* __restrict__ W,
       const float* __restrict__ bias, float* __restrict__ C, int M) {
    __shared__ float As[16][128];   // As[k][m] (A tile transposed)
    __shared__ float Bs[16][128];   // Bs[k][n]
    int tid  = threadIdx.x;
    int row0 = blockIdx.x * 128;
    int trow = (tid >> 4) << 3;     // 0..120
    int tcol = (tid & 15) << 3;     // 0..120
    float acc[8][8] = {};

    for (int k0 = 0; k0 < 128; k0 += 16) {
        // load A tile (128x16): 512 float4s, 2 per thread
        #pragma unroll
        for (int half = 0; half < 2; half++) {
            int f  = tid + half * 256;
            int m  = f >> 2;
            int kq = (f & 3) << 2;
            int gr = row0 + m;
            float4 a = (gr < M) ? *(const float4*)(A + (size_t)gr * 128 + k0 + kq)
                                : make_float4(0.f, 0.f, 0.f, 0.f);
            As[kq + 0][m] = a.x;
            As[kq + 1][m] = a.y;
            As[kq + 2][m] = a.z;
            As[kq + 3][m] = a.w;
        }
        // load B tile (16x128): 512 float4s, 2 per thread
        #pragma unroll
        for (int half = 0; half < 2; half++) {
            int f = tid + half * 256;
            int k = f >> 5;
            int n = (f & 31) << 2;
            *(float4*)&Bs[k][n] = *(const float4*)(W + (size_t)(k0 + k) * 128 + n);
        }
        __syncthreads();

        #pragma unroll
        for (int k = 0; k < 16; k++) {
            float a[8], b[8];
            *(float4*)&a[0] = *(const float4*)&As[k][trow];
            *(float4*)&a[4] = *(const float4*)&As[k][trow + 4];
            *(float4*)&b[0] = *(const float4*)&Bs[k][tcol];
            *(float4*)&b[4] = *(const float4*)&Bs[k][tcol + 4];
            #pragma unroll
            for (int i = 0; i < 8; i++)
                #pragma unroll
                for (int jj = 0; jj < 8; jj++)
                    acc[i][jj] += a[i] * b[jj];
        }
        __syncthreads();
    }

    float bv[8];
    *(float4*)&bv[0] = *(const float4*)&bias[tcol];
    *(float4*)&bv[4] = *(const float4*)&bias[tcol + 4];
    #pragma unroll
    for (int i = 0; i < 8; i++) {
        int gr = row0 + trow + i;
        if (gr < M) {
            float4 o0, o1;
            o0.x = acc[i][0] + bv[0];
            o0.y = acc[i][1] + bv[1];
            o0.z = acc[i][2] + bv[2];
            o0.w = acc[i][3] + bv[3];
            o1.x = acc[i][4] + bv[4];
            o1.y = acc[i][5] + bv[5];
            o1.z = acc[i][6] + bv[6];
            o1.w = acc[i][7] + bv[7];
            if (RELU) {
                o0.x = fmaxf(o0.x, 0.f); o0.y = fmaxf(o0.y, 0.f);
                o0.z = fmaxf(o0.z, 0.f); o0.w = fmaxf(o0.w, 0.f);
                o1.x = fmaxf(o1.x, 0.f); o1.y = fmaxf(o1.y, 0.f);
                o1.z = fmaxf(o1.z, 0.f); o1.w = fmaxf(o1.w, 0.f);
            }
            *(float4*)(C + (size_t)gr * 128 + tcol)     = o0;
            *(float4*)(C + (size_t)gr * 128 + tcol + 4) = o1;
        }
    }
}

// out[n] = h[n,:] . w2 + b2   (warp per node, warp-shuffle reduce)
__global__ void k_gemv(const float* __restrict__ h, const float* __restrict__ w2,
                       const float* __restrict__ b2, float* __restrict__ out) {
    int gw = (blockIdx.x * blockDim.x + threadIdx.x) >> 5;
    int lane = threadIdx.x & 31;
    if (gw >= NN) return;
    float4 v = *(const float4*)(h + (size_t)gw * 128 + lane * 4);
    float4 w = *(const float4*)(w2 + lane * 4);
    float s = v.x * w.x + v.y * w.y + v.z * w.z + v.w * w.w;
    #pragma unroll
    for (int o = 16; o; o >>= 1) s += __shfl_xor_sync(0xffffffffu, s, o);
    if (lane == 0) out[gw] = s + b2[0];
}

// ---------------------------------------------------------------
extern "C" void kernel_launch(void* const* d_in, const int* in_sizes, int n_in,
                              void* d_out, int out_size) {
    const float* nf   = (const float*)d_in[0];
    const int*   src  = (const int*)d_in[1];
    const int*   dst  = (const int*)d_in[2];
    const float* Wemb = (const float*)d_in[3];
    const float* bemb = (const float*)d_in[4];
    const float* Wg   = (const float*)d_in[5];
    const float* bg   = (const float*)d_in[6];
    const float* Wo1  = (const float*)d_in[7];
    const float* bo1  = (const float*)d_in[8];
    const float* Wo2  = (const float*)d_in[9];
    const float* bo2  = (const float*)d_in[10];
    float* out = (float*)d_out;

    float *hA, *hB;
    cudaGetSymbolAddress((void**)&hA, g_hA);
    cudaGetSymbolAddress((void**)&hB, g_hB);

    const int NB_EDGE = (NE + 255) / 256;
    const int NB_WARP = (NN * 32 + 255) / 256;   // warp-per-node kernels
    const int NB_GEMM = (NN + 127) / 128;

    // launch order chosen so ncu (-s 5 -c 1) captures the first k_spmm
    k_embed<<<(NN * EMB + 255) / 256, 256>>>(nf, Wemb, bemb);   // 0
    k_count<<<NB_EDGE, 256>>>(src, dst);                        // 1
    k_scanA<<<SCAN_BLOCKS, 256>>>();                            // 2
    k_scanB<<<SCAN_BLOCKS, 256>>>();                            // 3
    k_fill<<<NB_EDGE, 256>>>(src, dst);                         // 4

    for (int l = 0; l < 3; l++) {
        k_spmm<<<NB_WARP, 256>>>(hA, hB);                       // 5 (first iter)
        k_gemm<true><<<NB_GEMM, 256>>>(hB, Wg + (size_t)l * 128 * 128,
                                       bg + (size_t)l * 128, hA, NN);
    }
    k_gemm<true><<<NB_GEMM, 256>>>(hA, Wo1, bo1, hB, NN);
    k_gemv<<<NB_WARP, 256>>>(hB, Wo2, bo2, out);
}

// round 3
// speedup vs baseline: 1.9685x; 1.5456x over previous
#include <cuda_runtime.h>
#include <cstdint>

#define NN 50000
#define NE 640000
#define EMB 128
#define SCAN_BLOCKS 196   // 196*256 = 50176 >= NN

// ---- scratch (device globals; zero-initialized at load, re-zeroed each launch) ----
__device__ float g_hA[NN * EMB];      // 25.6 MB
__device__ float g_hB[NN * EMB];      // 25.6 MB
__device__ float g_norm_src[NN];
__device__ float g_norm_dst[NN];
__device__ int   g_deg_src[NN];       // zeroed at end of scanB each launch
__device__ int   g_deg_dst[NN];
__device__ int   g_row_ptr[NN + 1];
__device__ int   g_cursor[NN];
__device__ int   g_col[NE];
__device__ float g_colw[NE];
__device__ int   g_part[SCAN_BLOCKS];

// ---------------------------------------------------------------
// h = node_feats @ W_emb + b_emb   (IN_DIM = 4)
__global__ void k_embed(const float* __restrict__ nf,
                        const float* __restrict__ W,
                        const float* __restrict__ b) {
    int idx = blockIdx.x * blockDim.x + threadIdx.x;
    if (idx >= NN * EMB) return;
    int node = idx >> 7;
    int c = idx & 127;
    float a0 = nf[node * 4 + 0];
    float a1 = nf[node * 4 + 1];
    float a2 = nf[node * 4 + 2];
    float a3 = nf[node * 4 + 3];
    float acc = b[c];
    acc += a0 * W[0 * 128 + c];
    acc += a1 * W[1 * 128 + c];
    acc += a2 * W[2 * 128 + c];
    acc += a3 * W[3 * 128 + c];
    g_hA[idx] = acc;
}

__global__ void k_count(const int* __restrict__ src, const int* __restrict__ dst) {
    int e = blockIdx.x * blockDim.x + threadIdx.x;
    if (e < NE) {
        atomicAdd(&g_deg_src[src[e]], 1);
        atomicAdd(&g_deg_dst[dst[e]], 1);
    }
}

// per-block partial sums of deg_dst (256 elems / block)
__global__ void k_scanA() {
    __shared__ int sh[256];
    int i = blockIdx.x * 256 + threadIdx.x;
    int d = (i < NN) ? g_deg_dst[i] : 0;
    sh[threadIdx.x] = d;
    __syncthreads();
    #pragma unroll
    for (int off = 128; off; off >>= 1) {
        if (threadIdx.x < off) sh[threadIdx.x] += sh[threadIdx.x + off];
        __syncthreads();
    }
    if (threadIdx.x == 0) g_part[blockIdx.x] = sh[0];
}

// block b: prefix = sum(part[0..b-1]); local exclusive scan; write row_ptr/cursor;
// also compute both norms and zero the degree counters for the next launch.
__global__ void k_scanB() {
    __shared__ int sh[256];
    __shared__ int pre;
    int tid = threadIdx.x;
    int b = blockIdx.x;
    // prefix of earlier blocks
    int pv = (tid < b) ? g_part[tid] : 0;
    sh[tid] = pv;
    __syncthreads();
    #pragma unroll
    for (int off = 128; off; off >>= 1) {
        if (tid < off) sh[tid] += sh[tid + off];
        __syncthreads();
    }
    if (tid == 0) pre = sh[0];
    __syncthreads();
    int prefix = pre;
    __syncthreads();

    int i = b * 256 + tid;
    int d = (i < NN) ? g_deg_dst[i] : 0;
    // inclusive scan over the block's 256 degrees
    sh[tid] = d;
    __syncthreads();
    #pragma unroll
    for (int off = 1; off < 256; off <<= 1) {
        int v = (tid >= off) ? sh[tid - off] : 0;
        __syncthreads();
        sh[tid] += v;
        __syncthreads();
    }
    int incl = sh[tid];
    int excl = incl - d;
    if (i < NN) {
        int base = prefix + excl;
        g_row_ptr[i] = base;
        g_cursor[i]  = base;
        if (i == NN - 1) g_row_ptr[NN] = prefix + incl;
        int ds = g_deg_src[i];
        g_norm_dst[i] = rsqrtf((float)max(d, 1));
        g_norm_src[i] = rsqrtf((float)max(ds, 1));
        g_deg_dst[i] = 0;   // leave zeroed for next launch
        g_deg_src[i] = 0;
    }
}

__global__ void k_fill(const int* __restrict__ src, const int* __restrict__ dst) {
    int e = blockIdx.x * blockDim.x + threadIdx.x;
    if (e < NE) {
        int s = src[e];
        int pos = atomicAdd(&g_cursor[dst[e]], 1);
        g_col[pos]  = s;
        g_colw[pos] = g_norm_src[s];   // fold src-side norm into edge weight
    }
}

// CSR aggregation: one warp per destination node, lane owns 4 floats (float4)
__global__ void k_spmm(const float* __restrict__ h, float* __restrict__ out) {
    int gw = (blockIdx.x * blockDim.x + threadIdx.x) >> 5;
    int lane = threadIdx.x & 31;
    if (gw >= NN) return;
    int beg = g_row_ptr[gw];
    int end = g_row_ptr[gw + 1];
    float4 acc = make_float4(0.f, 0.f, 0.f, 0.f);
    int j = beg;
    for (; j + 4 <= end; j += 4) {
        int   s0 = __ldg(&g_col[j]);
        int   s1 = __ldg(&g_col[j + 1]);
        int   s2 = __ldg(&g_col[j + 2]);
        int   s3 = __ldg(&g_col[j + 3]);
        float w0 = __ldg(&g_colw[j]);
        float w1 = __ldg(&g_colw[j + 1]);
        float w2 = __ldg(&g_colw[j + 2]);
        float w3 = __ldg(&g_colw[j + 3]);
        float4 v0 = *(const float4*)(h + (size_t)s0 * EMB + lane * 4);
        float4 v1 = *(const float4*)(h + (size_t)s1 * EMB + lane * 4);
        float4 v2 = *(const float4*)(h + (size_t)s2 * EMB + lane * 4);
        float4 v3 = *(const float4*)(h + (size_t)s3 * EMB + lane * 4);
        acc.x += w0 * v0.x + w1 * v1.x + w2 * v2.x + w3 * v3.x;
        acc.y += w0 * v0.y + w1 * v1.y + w2 * v2.y + w3 * v3.y;
        acc.z += w0 * v0.z + w1 * v1.z + w2 * v2.z + w3 * v3.z;
        acc.w += w0 * v0.w + w1 * v1.w + w2 * v2.w + w3 * v3.w;
    }
    for (; j < end; j++) {
        int   s0 = __ldg(&g_col[j]);
        float w0 = __ldg(&g_colw[j]);
        float4 v0 = *(const float4*)(h + (size_t)s0 * EMB + lane * 4);
        acc.x += w0 * v0.x;
        acc.y += w0 * v0.y;
        acc.z += w0 * v0.z;
        acc.w += w0 * v0.w;
    }
    float nd = g_norm_dst[gw];
    acc.x *= nd; acc.y *= nd; acc.z *= nd; acc.w *= nd;
    *(float4*)(out + (size_t)gw * EMB + lane * 4) = acc;
}

// ---------------------------------------------------------------
// Tensor-core GEMM: C[M,128] = relu(A[M,128] @ W[128,128] + bias)
// mma.sync.m16n8k8 tf32, fp32 accumulate.
// CTA: 256 thr (8 warps, 4x2), tile 128x128, BK=32. Warp tile 32(m) x 64(n).
__device__ __forceinline__ uint32_t f2tf32(float f) {
    uint32_t r;
    asm("cvt.rna.tf32.f32 %0, %1;" : "=r"(r) : "f"(f));
    return r;
}

template <bool RELU>
__global__ void __launch_bounds__(256)
k_gemm_tc(const float* __restrict__ A, const float* __restrict__ W,
          const float* __restrict__ bias, float* __restrict__ C, int M) {
    __shared__ uint32_t As[32][132];   // tf32 bits, [k][m], +4 pad
    __shared__ uint32_t Ws[32][132];   // tf32 bits, [k][n], +4 pad
    int tid  = threadIdx.x;
    int warp = tid >> 5;
    int lane = tid & 31;
    int wm = warp & 3;      // 4 warps along m: 32 rows each
    int wn = warp >> 2;     // 2 warps along n: 64 cols each
    int lg = lane >> 2;     // group id 0..7
    int lt = lane & 3;      // thread-in-group 0..3
    int row0 = blockIdx.x * 128;

    float c[2][8][4];
    #pragma unroll
    for (int i = 0; i < 2; i++)
        #pragma unroll
        for (int j = 0; j < 8; j++)
            #pragma unroll
            for (int q = 0; q < 4; q++) c[i][j][q] = 0.f;

    for (int k0 = 0; k0 < 128; k0 += 32) {
        // A tile 128x32 -> As[k][m], converted to tf32
        #pragma unroll
        for (int it = 0; it < 4; it++) {
            int f  = tid + it * 256;        // 0..1023
            int m  = f >> 3;                // 0..127
            int kq = (f & 7) << 2;          // 0,4,...,28
            int gr = row0 + m;
            float4 a = (gr < M) ? *(const float4*)(A + (size_t)gr * 128 + k0 + kq)
                                : make_float4(0.f, 0.f, 0.f, 0.f);
            As[kq + 0][m] = f2tf32(a.x);
            As[kq + 1][m] = f2tf32(a.y);
            As[kq + 2][m] = f2tf32(a.z);
            As[kq + 3][m] = f2tf32(a.w);
        }
        // W tile 32x128 -> Ws[k][n]
        #pragma unroll
        for (int it = 0; it < 4; it++) {
            int f = tid + it * 256;
            int k = f >> 5;                 // 0..31
            int n = (f & 31) << 2;          // 0..124
            float4 w = *(const float4*)(W + (size_t)(k0 + k) * 128 + n);
            Ws[k][n + 0] = f2tf32(w.x);
            Ws[k][n + 1] = f2tf32(w.y);
            Ws[k][n + 2] = f2tf32(w.z);
            Ws[k][n + 3] = f2tf32(w.w);
        }
        __syncthreads();

        #pragma unroll
        for (int ks = 0; ks < 32; ks += 8) {
            uint32_t af[2][4];
            #pragma unroll
            for (int mt = 0; mt < 2; mt++) {
                int m = wm * 32 + mt * 16 + lg;
                af[mt][0] = As[ks + lt][m];
                af[mt][1] = As[ks + lt][m + 8];
                af[mt][2] = As[ks + 4 + lt][m];
                af[mt][3] = As[ks + 4 + lt][m + 8];
            }
            #pragma unroll
            for (int nt = 0; nt < 8; nt++) {
                int n = wn * 64 + nt * 8 + lg;
                uint32_t b0 = Ws[ks + lt][n];
                uint32_t b1 = Ws[ks + 4 + lt][n];
                #pragma unroll
                for (int mt = 0; mt < 2; mt++) {
                    asm volatile(
                        "mma.sync.aligned.m16n8k8.row.col.f32.tf32.tf32.f32 "
                        "{%0,%1,%2,%3}, {%4,%5,%6,%7}, {%8,%9}, {%0,%1,%2,%3};"
                        : "+f"(c[mt][nt][0]), "+f"(c[mt][nt][1]),
                          "+f"(c[mt][nt][2]), "+f"(c[mt][nt][3])
                        : "r"(af[mt][0]), "r"(af[mt][1]),
                          "r"(af[mt][2]), "r"(af[mt][3]),
                          "r"(b0), "r"(b1));
                }
            }
        }
        __syncthreads();
    }

    // epilogue: bias + relu, float2 stores
    #pragma unroll
    for (int nt = 0; nt < 8; nt++) {
        int col = wn * 64 + nt * 8 + 2 * lt;
        float2 bv = *(const float2*)(bias + col);
        #pragma unroll
        for (int mt = 0; mt < 2; mt++) {
            int r = row0 + wm * 32 + mt * 16 + lg;
            float2 o0, o1;
            o0.x = c[mt][nt][0] + bv.x;
            o0.y = c[mt][nt][1] + bv.y;
            o1.x = c[mt][nt][2] + bv.x;
            o1.y = c[mt][nt][3] + bv.y;
            if (RELU) {
                o0.x = fmaxf(o0.x, 0.f); o0.y = fmaxf(o0.y, 0.f);
                o1.x = fmaxf(o1.x, 0.f); o1.y = fmaxf(o1.y, 0.f);
            }
            if (r < M)     *(float2*)(C + (size_t)r * 128 + col)       = o0;
            if (r + 8 < M) *(float2*)(C + (size_t)(r + 8) * 128 + col) = o1;
        }
    }
}

// out[n] = h[n,:] . w2 + b2   (warp per node, warp-shuffle reduce)
__global__ void k_gemv(const float* __restrict__ h, const float* __restrict__ w2,
                       const float* __restrict__ b2, float* __restrict__ out) {
    int gw = (blockIdx.x * blockDim.x + threadIdx.x) >> 5;
    int lane = threadIdx.x & 31;
    if (gw >= NN) return;
    float4 v = *(const float4*)(h + (size_t)gw * 128 + lane * 4);
    float4 w = *(const float4*)(w2 + lane * 4);
    float s = v.x * w.x + v.y * w.y + v.z * w.z + v.w * w.w;
    #pragma unroll
    for (int o = 16; o; o >>= 1) s += __shfl_xor_sync(0xffffffffu, s, o);
    if (lane == 0) out[gw] = s + b2[0];
}

// ---------------------------------------------------------------
extern "C" void kernel_launch(void* const* d_in, const int* in_sizes, int n_in,
                              void* d_out, int out_size) {
    const float* nf   = (const float*)d_in[0];
    const int*   src  = (const int*)d_in[1];
    const int*   dst  = (const int*)d_in[2];
    const float* Wemb = (const float*)d_in[3];
    const float* bemb = (const float*)d_in[4];
    const float* Wg   = (const float*)d_in[5];
    const float* bg   = (const float*)d_in[6];
    const float* Wo1  = (const float*)d_in[7];
    const float* bo1  = (const float*)d_in[8];
    const float* Wo2  = (const float*)d_in[9];
    const float* bo2  = (const float*)d_in[10];
    float* out = (float*)d_out;

    float *hA, *hB;
    cudaGetSymbolAddress((void**)&hA, g_hA);
    cudaGetSymbolAddress((void**)&hB, g_hB);

    const int NB_EDGE = (NE + 255) / 256;
    const int NB_WARP = (NN * 32 + 255) / 256;   // warp-per-node kernels
    const int NB_GEMM = (NN + 127) / 128;

    k_embed<<<(NN * EMB + 255) / 256, 256>>>(nf, Wemb, bemb);   // 0
    k_count<<<NB_EDGE, 256>>>(src, dst);                        // 1
    k_scanA<<<SCAN_BLOCKS, 256>>>();                            // 2
    k_scanB<<<SCAN_BLOCKS, 256>>>();                            // 3
    k_fill<<<NB_EDGE, 256>>>(src, dst);                         // 4

    for (int l = 0; l < 3; l++) {
        k_spmm<<<NB_WARP, 256>>>(hA, hB);                       // 5 (first iter)
        k_gemm_tc<true><<<NB_GEMM, 256>>>(hB, Wg + (size_t)l * 128 * 128,
                                          bg + (size_t)l * 128, hA, NN);
    }
    k_gemm_tc<true><<<NB_GEMM, 256>>>(hA, Wo1, bo1, hB, NN);
    k_gemv<<<NB_WARP, 256>>>(hB, Wo2, bo2, out);
}